// round 1
// baseline (speedup 1.0000x reference)
#include <cuda_runtime.h>
#include <cstdint>

// Problem constants (fixed by the dataset)
#define Bc 4
#define Qc 4096
#define Cc 256
#define Mh 8
#define Lc 4
#define Pc 4
#define Dc 32
#define Nc 21760
#define BQ (Bc*Qc)          // 16384

// Scratch (device globals; allocation-free rule)
__device__ float g_vp[(size_t)Bc*Mh*Nc*Dc];   // [B,M,N,D] head-major value proj
__device__ float g_logits[(size_t)BQ*128];    // attn logits [BQ, M*L*P]
__device__ float g_off[(size_t)BQ*256];       // offsets    [BQ, M*L*P*2]
__device__ float g_heads[(size_t)BQ*256];     // sampled    [BQ, C]

// ---------------------------------------------------------------------------
// Tiled fp32 GEMM: C[Md,Nd] = A[Md,K] @ B[K,Nd] + bias[Nd]
// BM=BN=64, BK=16, 256 threads, 4x4 per thread.
// STORE_MODE 0: row-major store. 1: v_proj permuted store -> g_vp[B,M,N,D].
// ---------------------------------------------------------------------------
template<int STORE_MODE>
__global__ void gemm64(const float* __restrict__ A, const float* __restrict__ Bm,
                       const float* __restrict__ bias, float* __restrict__ Cd,
                       int Md, int Nd, int K) {
    __shared__ float As[16][64];
    __shared__ float Bs[16][64];
    const int tid = threadIdx.x;
    const int rowBase = blockIdx.y * 64;
    const int colBase = blockIdx.x * 64;

    const int aRow = tid >> 2;           // 0..63
    const int aCol = (tid & 3) * 4;      // 0,4,8,12
    const int bRow = tid >> 4;           // 0..15
    const int bCol = (tid & 15) * 4;     // 0..60

    const int ty = tid >> 4;             // 0..15
    const int tx = tid & 15;             // 0..15

    float acc[4][4];
    #pragma unroll
    for (int i = 0; i < 4; i++)
        #pragma unroll
        for (int j = 0; j < 4; j++) acc[i][j] = 0.f;

    for (int k0 = 0; k0 < K; k0 += 16) {
        float4 av = *(const float4*)(A + (size_t)(rowBase + aRow) * K + k0 + aCol);
        As[aCol + 0][aRow] = av.x;
        As[aCol + 1][aRow] = av.y;
        As[aCol + 2][aRow] = av.z;
        As[aCol + 3][aRow] = av.w;
        float4 bv = *(const float4*)(Bm + (size_t)(k0 + bRow) * Nd + colBase + bCol);
        *(float4*)&Bs[bRow][bCol] = bv;
        __syncthreads();

        #pragma unroll
        for (int k = 0; k < 16; k++) {
            float4 ra = *(const float4*)&As[k][ty * 4];
            float4 rb = *(const float4*)&Bs[k][tx * 4];
            float a4[4] = {ra.x, ra.y, ra.z, ra.w};
            float b4[4] = {rb.x, rb.y, rb.z, rb.w};
            #pragma unroll
            for (int i = 0; i < 4; i++)
                #pragma unroll
                for (int j = 0; j < 4; j++) acc[i][j] += a4[i] * b4[j];
        }
        __syncthreads();
    }

    #pragma unroll
    for (int i = 0; i < 4; i++) {
        int row = rowBase + ty * 4 + i;
        #pragma unroll
        for (int j = 0; j < 4; j++) {
            int col = colBase + tx * 4 + j;
            float v = acc[i][j] + bias[col];
            if (STORE_MODE == 0) {
                Cd[(size_t)row * Nd + col] = v;
            } else {
                // row = b*N + n ; col = m*32 + d  ->  vp[((b*M+m)*N+n)*32+d]
                int b = row / Nc, n = row - b * Nc;
                int m = col >> 5, d = col & 31;
                Cd[((((size_t)b * Mh + m) * Nc) + n) * Dc + d] = v;
            }
        }
    }
}

// ---------------------------------------------------------------------------
// Sampling: one block per (b,q), one warp per head. Softmax over 16 (L*P)
// logits via warp shuffle, then bilinear gather from head-major g_vp.
// ---------------------------------------------------------------------------
__global__ void sample_kernel(const float* __restrict__ p,
                              const int* __restrict__ shapes,
                              const int* __restrict__ level_index) {
    const int bq = blockIdx.x;            // 0..BQ-1
    const int b  = bq >> 12;              // Q=4096
    const int tid = threadIdx.x;
    const int m = tid >> 5;               // warp = head
    const int lane = tid & 31;

    __shared__ float s_attn[Mh][16];
    __shared__ float s_off[Mh][32];
    __shared__ float s_p[Lc * 2];
    __shared__ int   s_sh[Lc * 2];
    __shared__ int   s_base[Lc];

    if (tid < Lc * 2) {
        s_p[tid]  = p[(size_t)bq * (Lc * 2) + tid];
        s_sh[tid] = shapes[tid];
    }
    if (tid >= 8 && tid < 12) s_base[tid - 8] = level_index[tid - 8];

    // per-head offsets (32 floats)
    s_off[m][lane] = g_off[(size_t)bq * 256 + m * 32 + lane];

    // softmax over 16 logits
    float lg = (lane < 16) ? g_logits[(size_t)bq * 128 + m * 16 + lane] : -1e30f;
    float mx = lg;
    #pragma unroll
    for (int s = 16; s; s >>= 1) mx = fmaxf(mx, __shfl_xor_sync(0xffffffffu, mx, s));
    float e = (lane < 16) ? __expf(lg - mx) : 0.f;
    float sum = e;
    #pragma unroll
    for (int s = 16; s; s >>= 1) sum += __shfl_xor_sync(0xffffffffu, sum, s);
    if (lane < 16) s_attn[m][lane] = e / sum;
    __syncthreads();

    float acc = 0.f;
    #pragma unroll
    for (int pt = 0; pt < 16; pt++) {
        const int l = pt >> 2;
        const int H = s_sh[l * 2 + 0];
        const int W = s_sh[l * 2 + 1];
        const float Wf = (float)W, Hf = (float)H;
        float locx = s_p[l * 2 + 0] + s_off[m][pt * 2 + 0] / Wf;
        float locy = s_p[l * 2 + 1] + s_off[m][pt * 2 + 1] / Hf;
        float x = locx * Wf - 0.5f;
        float y = locy * Hf - 0.5f;
        float x0f = floorf(x), y0f = floorf(y);
        float lx = x - x0f, ly = y - y0f;
        int x0 = (int)x0f, y0 = (int)y0f;
        float aw = s_attn[m][pt];

        const float* vpb = g_vp + ((((size_t)b * Mh + m) * Nc) + s_base[l]) * Dc;

        float w00 = aw * (1.f - lx) * (1.f - ly);
        float w10 = aw * lx * (1.f - ly);
        float w01 = aw * (1.f - lx) * ly;
        float w11 = aw * lx * ly;

        if (x0 >= 0 && x0 < W && y0 >= 0 && y0 < H)
            acc += w00 * vpb[((size_t)y0 * W + x0) * Dc + lane];
        if (x0 + 1 >= 0 && x0 + 1 < W && y0 >= 0 && y0 < H)
            acc += w10 * vpb[((size_t)y0 * W + x0 + 1) * Dc + lane];
        if (x0 >= 0 && x0 < W && y0 + 1 >= 0 && y0 + 1 < H)
            acc += w01 * vpb[((size_t)(y0 + 1) * W + x0) * Dc + lane];
        if (x0 + 1 >= 0 && x0 + 1 < W && y0 + 1 >= 0 && y0 + 1 < H)
            acc += w11 * vpb[((size_t)(y0 + 1) * W + x0 + 1) * Dc + lane];
    }

    g_heads[(size_t)bq * 256 + m * 32 + lane] = acc;
}

// ---------------------------------------------------------------------------
extern "C" void kernel_launch(void* const* d_in, const int* in_sizes, int n_in,
                              void* d_out, int out_size) {
    const float* q       = (const float*)d_in[0];
    const float* p       = (const float*)d_in[1];
    const float* v       = (const float*)d_in[2];
    const int*   shapes  = (const int*)d_in[3];
    const int*   lvl_idx = (const int*)d_in[4];
    const float* W_off   = (const float*)d_in[5];
    const float* b_off   = (const float*)d_in[6];
    const float* W_attn  = (const float*)d_in[7];
    const float* b_attn  = (const float*)d_in[8];
    const float* W_val   = (const float*)d_in[9];
    const float* b_val   = (const float*)d_in[10];
    const float* W_out   = (const float*)d_in[11];
    const float* b_out   = (const float*)d_in[12];
    float* out = (float*)d_out;

    float* vp;     cudaGetSymbolAddress((void**)&vp,     g_vp);
    float* logits; cudaGetSymbolAddress((void**)&logits, g_logits);
    float* off;    cudaGetSymbolAddress((void**)&off,    g_off);
    float* heads;  cudaGetSymbolAddress((void**)&heads,  g_heads);

    // 1) value projection: [B*N,256] @ [256,256] -> g_vp (head-major store)
    {
        dim3 grid(Cc / 64, (Bc * Nc) / 64);
        gemm64<1><<<grid, 256>>>(v, W_val, b_val, vp, Bc * Nc, Cc, Cc);
    }
    // 2) attention logits: [BQ,256] @ [256,128]
    {
        dim3 grid(128 / 64, BQ / 64);
        gemm64<0><<<grid, 256>>>(q, W_attn, b_attn, logits, BQ, 128, Cc);
    }
    // 3) offsets: [BQ,256] @ [256,256]
    {
        dim3 grid(256 / 64, BQ / 64);
        gemm64<0><<<grid, 256>>>(q, W_off, b_off, off, BQ, 256, Cc);
    }
    // 4) softmax + bilinear sampling -> g_heads
    sample_kernel<<<BQ, 256>>>(p, shapes, lvl_idx);
    // 5) output projection: [BQ,256] @ [256,256] -> d_out
    {
        dim3 grid(256 / 64, BQ / 64);
        gemm64<0><<<grid, 256>>>(heads, W_out, b_out, out, BQ, 256, Cc);
    }
}

// round 2
// speedup vs baseline: 1.5794x; 1.5794x over previous
#include <cuda_runtime.h>
#include <mma.h>
#include <cstdint>

using namespace nvcuda;

// Problem constants (fixed by the dataset)
#define Bc 4
#define Qc 4096
#define Cc 256
#define Mh 8
#define Lc 4
#define Pc 4
#define Dc 32
#define Nc 21760
#define BQ (Bc*Qc)          // 16384

// Scratch (device globals; allocation-free rule)
__device__ float g_vp[(size_t)Bc*Mh*Nc*Dc];   // [B,M,N,D] head-major value proj
__device__ float g_logits[(size_t)BQ*128];    // attn logits [BQ, M*L*P]
__device__ float g_off[(size_t)BQ*256];       // offsets    [BQ, M*L*P*2]
__device__ float g_heads[(size_t)BQ*256];     // sampled    [BQ, C]

// ---------------------------------------------------------------------------
// Tensor-core tf32 GEMM: C[Md,Nd] = A[Md,K] @ B[K,Nd] + bias[Nd]
// BM=128, BN=64, BK=32. 256 threads = 8 warps in 4x2 layout; each warp 32x32
// via 2x2 wmma m16n16k8 fragments.
// SPLIT=1: 3xTF32 error-compensated (A,B split into hi+lo; hh+hl+lh terms).
// STORE_MODE 0: row-major store. 1: permuted store -> g_vp[B,M,N,D].
// ---------------------------------------------------------------------------
template<int SPLIT, int STORE_MODE>
__global__ void gemm_tc(const float* __restrict__ A, const float* __restrict__ Bm,
                        const float* __restrict__ bias, float* __restrict__ Cd,
                        int Nd, int K) {
    constexpr int BM = 128, BN = 64, BK = 32;
    constexpr int BKp = 40;   // A smem row pitch
    constexpr int BNp = 72;   // B smem row pitch
    constexpr int ASZ = BM * BKp;      // 5120 floats
    constexpr int BSZ = BK * BNp;      // 2304 floats
    constexpr int EPIP = 68;           // epilogue pitch
    constexpr int EPISZ = BM * EPIP;   // 8704 floats
    constexpr int LOADSZ = (SPLIT ? 2 : 1) * (ASZ + BSZ);
    constexpr int SMEMF = (LOADSZ > EPISZ) ? LOADSZ : EPISZ;

    __shared__ __align__(16) float smem[SMEMF];
    float* As_hi = smem;
    float* As_lo = smem + ASZ;                       // only if SPLIT
    float* Bs_hi = smem + (SPLIT ? 2 : 1) * ASZ;
    float* Bs_lo = Bs_hi + BSZ;                      // only if SPLIT
    float* Cs    = smem;

    const int tid = threadIdx.x;
    const int wid = tid >> 5;
    const int warpRow = (wid >> 1) * 32;   // 0,32,64,96
    const int warpCol = (wid & 1) * 32;    // 0,32
    const int rowBase = blockIdx.y * BM;
    const int colBase = blockIdx.x * BN;

    wmma::fragment<wmma::accumulator, 16, 16, 8, float> acc[2][2];
    #pragma unroll
    for (int i = 0; i < 2; i++)
        #pragma unroll
        for (int j = 0; j < 2; j++) wmma::fill_fragment(acc[i][j], 0.f);

    for (int k0 = 0; k0 < K; k0 += BK) {
        // load A tile: 128x32 floats = 1024 float4, 4 per thread
        #pragma unroll
        for (int i = 0; i < 4; i++) {
            int lin = tid + i * 256;
            int r = lin >> 3, cv = (lin & 7) * 4;
            float4 v = *(const float4*)(A + (size_t)(rowBase + r) * K + k0 + cv);
            float h;
            h = wmma::__float_to_tf32(v.x); As_hi[r*BKp+cv+0] = h; if (SPLIT) As_lo[r*BKp+cv+0] = wmma::__float_to_tf32(v.x - h);
            h = wmma::__float_to_tf32(v.y); As_hi[r*BKp+cv+1] = h; if (SPLIT) As_lo[r*BKp+cv+1] = wmma::__float_to_tf32(v.y - h);
            h = wmma::__float_to_tf32(v.z); As_hi[r*BKp+cv+2] = h; if (SPLIT) As_lo[r*BKp+cv+2] = wmma::__float_to_tf32(v.z - h);
            h = wmma::__float_to_tf32(v.w); As_hi[r*BKp+cv+3] = h; if (SPLIT) As_lo[r*BKp+cv+3] = wmma::__float_to_tf32(v.w - h);
        }
        // load B tile: 32x64 floats = 512 float4, 2 per thread
        #pragma unroll
        for (int i = 0; i < 2; i++) {
            int lin = tid + i * 256;
            int r = lin >> 4, cv = (lin & 15) * 4;
            float4 v = *(const float4*)(Bm + (size_t)(k0 + r) * Nd + colBase + cv);
            float h;
            h = wmma::__float_to_tf32(v.x); Bs_hi[r*BNp+cv+0] = h; if (SPLIT) Bs_lo[r*BNp+cv+0] = wmma::__float_to_tf32(v.x - h);
            h = wmma::__float_to_tf32(v.y); Bs_hi[r*BNp+cv+1] = h; if (SPLIT) Bs_lo[r*BNp+cv+1] = wmma::__float_to_tf32(v.y - h);
            h = wmma::__float_to_tf32(v.z); Bs_hi[r*BNp+cv+2] = h; if (SPLIT) Bs_lo[r*BNp+cv+2] = wmma::__float_to_tf32(v.z - h);
            h = wmma::__float_to_tf32(v.w); Bs_hi[r*BNp+cv+3] = h; if (SPLIT) Bs_lo[r*BNp+cv+3] = wmma::__float_to_tf32(v.w - h);
        }
        __syncthreads();

        #pragma unroll
        for (int kk = 0; kk < BK; kk += 8) {
            wmma::fragment<wmma::matrix_a, 16, 16, 8, wmma::precision::tf32, wmma::row_major> ah[2], al[2];
            wmma::fragment<wmma::matrix_b, 16, 16, 8, wmma::precision::tf32, wmma::row_major> bh[2], bl[2];
            #pragma unroll
            for (int i = 0; i < 2; i++) {
                wmma::load_matrix_sync(ah[i], &As_hi[(warpRow + i*16)*BKp + kk], BKp);
                if (SPLIT) wmma::load_matrix_sync(al[i], &As_lo[(warpRow + i*16)*BKp + kk], BKp);
            }
            #pragma unroll
            for (int j = 0; j < 2; j++) {
                wmma::load_matrix_sync(bh[j], &Bs_hi[kk*BNp + warpCol + j*16], BNp);
                if (SPLIT) wmma::load_matrix_sync(bl[j], &Bs_lo[kk*BNp + warpCol + j*16], BNp);
            }
            #pragma unroll
            for (int i = 0; i < 2; i++)
                #pragma unroll
                for (int j = 0; j < 2; j++) {
                    wmma::mma_sync(acc[i][j], ah[i], bh[j], acc[i][j]);
                    if (SPLIT) {
                        wmma::mma_sync(acc[i][j], ah[i], bl[j], acc[i][j]);
                        wmma::mma_sync(acc[i][j], al[i], bh[j], acc[i][j]);
                    }
                }
        }
        __syncthreads();
    }

    // epilogue: frags -> smem -> (bias, permute) -> global
    #pragma unroll
    for (int i = 0; i < 2; i++)
        #pragma unroll
        for (int j = 0; j < 2; j++)
            wmma::store_matrix_sync(&Cs[(warpRow + i*16)*EPIP + warpCol + j*16],
                                    acc[i][j], EPIP, wmma::mem_row_major);
    __syncthreads();

    // 128x64 = 2048 float4, 8 per thread
    #pragma unroll
    for (int i = 0; i < 8; i++) {
        int lin = tid + i * 256;
        int r = lin >> 4, cv = (lin & 15) * 4;
        float4 c = *(const float4*)&Cs[r*EPIP + cv];
        float4 bb = *(const float4*)(bias + colBase + cv);
        c.x += bb.x; c.y += bb.y; c.z += bb.z; c.w += bb.w;
        int rowG = rowBase + r;
        int colG = colBase + cv;
        if (STORE_MODE == 0) {
            *(float4*)(Cd + (size_t)rowG * Nd + colG) = c;
        } else {
            // rowG = b*N + n ; colG = m*32 + d  ->  vp[((b*8+m)*N+n)*32+d]
            int b = rowG / Nc, n = rowG - b * Nc;
            int m = colG >> 5, d = colG & 31;
            *(float4*)(Cd + ((((size_t)b * Mh + m) * Nc) + n) * Dc + d) = c;
        }
    }
}

// ---------------------------------------------------------------------------
// Warp-autonomous sampling: one warp per (b,q,head). No smem, no block sync.
// Softmax over 16 logits + per-point params via warp shuffle; lane = channel d.
// All index math in 32-bit.
// ---------------------------------------------------------------------------
__global__ void sample_kernel(const float* __restrict__ p,
                              const int* __restrict__ shapes,
                              const int* __restrict__ level_index) {
    const int w = (blockIdx.x * blockDim.x + threadIdx.x) >> 5;
    const int lane = threadIdx.x & 31;
    const int bq = w >> 3;
    const int m = w & 7;
    const int b = bq >> 12;

    // per-lane offset value (lane i holds off[m*32+i])
    const float offv = g_off[bq * 256 + m * 32 + lane];

    // softmax over 16 logits (lanes 0..15 hold them)
    float lg = (lane < 16) ? g_logits[bq * 128 + m * 16 + lane] : -1e30f;
    float mx = lg;
    #pragma unroll
    for (int s = 8; s; s >>= 1) mx = fmaxf(mx, __shfl_xor_sync(0xffffffffu, mx, s));
    float e = (lane < 16) ? __expf(lg - mx) : 0.f;
    float sum = e;
    #pragma unroll
    for (int s = 8; s; s >>= 1) sum += __shfl_xor_sync(0xffffffffu, sum, s);
    const float attn = e / sum;   // valid on lanes 0..15

    const int vp_head = (b * Mh + m) * Nc;
    float acc = 0.f;

    #pragma unroll
    for (int l = 0; l < Lc; l++) {
        const int H  = shapes[2*l + 0];
        const int Wd = shapes[2*l + 1];
        const float Hf = (float)H, Wf = (float)Wd;
        const float px = p[bq * (Lc*2) + 2*l + 0];
        const float py = p[bq * (Lc*2) + 2*l + 1];
        const float* __restrict__ vpb = g_vp + ((size_t)(vp_head + level_index[l]) << 5);

        #pragma unroll
        for (int pp = 0; pp < Pc; pp++) {
            const int pt = l * Pc + pp;
            const float ox = __shfl_sync(0xffffffffu, offv, pt*2 + 0);
            const float oy = __shfl_sync(0xffffffffu, offv, pt*2 + 1);
            const float aw = __shfl_sync(0xffffffffu, attn, pt);

            // (p + off/W)*W - 0.5 == p*W + off - 0.5 (exact in math; 1-ulp fp diff)
            const float x = fmaf(px, Wf, ox) - 0.5f;
            const float y = fmaf(py, Hf, oy) - 0.5f;
            const float x0f = floorf(x), y0f = floorf(y);
            const float lx = x - x0f, ly = y - y0f;
            const int x0 = (int)x0f, y0 = (int)y0f;

            const float w11 = aw * lx * ly;
            const float w10 = aw * lx - w11;          // aw*lx*(1-ly)
            const float w01 = aw * ly - w11;          // aw*(1-lx)*ly
            const float w00 = aw - w10 - w01 - w11;   // aw*(1-lx)*(1-ly)

            const bool inx0 = (unsigned)x0       < (unsigned)Wd;
            const bool inx1 = (unsigned)(x0 + 1) < (unsigned)Wd;
            const bool iny0 = (unsigned)y0       < (unsigned)H;
            const bool iny1 = (unsigned)(y0 + 1) < (unsigned)H;

            const int r0 = y0 * Wd + x0;
            const int r1 = r0 + Wd;
            if (inx0 & iny0) acc = fmaf(w00, vpb[(r0 << 5) + lane], acc);
            if (inx1 & iny0) acc = fmaf(w10, vpb[((r0 + 1) << 5) + lane], acc);
            if (inx0 & iny1) acc = fmaf(w01, vpb[(r1 << 5) + lane], acc);
            if (inx1 & iny1) acc = fmaf(w11, vpb[((r1 + 1) << 5) + lane], acc);
        }
    }

    g_heads[bq * 256 + m * 32 + lane] = acc;
}

// ---------------------------------------------------------------------------
extern "C" void kernel_launch(void* const* d_in, const int* in_sizes, int n_in,
                              void* d_out, int out_size) {
    const float* q       = (const float*)d_in[0];
    const float* p       = (const float*)d_in[1];
    const float* v       = (const float*)d_in[2];
    const int*   shapes  = (const int*)d_in[3];
    const int*   lvl_idx = (const int*)d_in[4];
    const float* W_off   = (const float*)d_in[5];
    const float* b_off   = (const float*)d_in[6];
    const float* W_attn  = (const float*)d_in[7];
    const float* b_attn  = (const float*)d_in[8];
    const float* W_val   = (const float*)d_in[9];
    const float* b_val   = (const float*)d_in[10];
    const float* W_out   = (const float*)d_in[11];
    const float* b_out   = (const float*)d_in[12];
    float* out = (float*)d_out;

    float* vp;     cudaGetSymbolAddress((void**)&vp,     g_vp);
    float* logits; cudaGetSymbolAddress((void**)&logits, g_logits);
    float* off;    cudaGetSymbolAddress((void**)&off,    g_off);
    float* heads;  cudaGetSymbolAddress((void**)&heads,  g_heads);

    // 1) value projection: [B*N,256] @ [256,256] -> g_vp (head-major store), tf32
    {
        dim3 grid(Cc / 64, (Bc * Nc) / 128);   // (4, 680)
        gemm_tc<0, 1><<<grid, 256>>>(v, W_val, b_val, vp, Cc, Cc);
    }
    // 2) attention logits: [BQ,256] @ [256,128], tf32
    {
        dim3 grid(128 / 64, BQ / 128);
        gemm_tc<0, 0><<<grid, 256>>>(q, W_attn, b_attn, logits, 128, Cc);
    }
    // 3) offsets: [BQ,256] @ [256,256], 3xTF32 (position-critical precision)
    {
        dim3 grid(256 / 64, BQ / 128);
        gemm_tc<1, 0><<<grid, 256>>>(q, W_off, b_off, off, 256, Cc);
    }
    // 4) softmax + bilinear sampling -> g_heads (warp per (b,q,m))
    sample_kernel<<<(BQ * Mh) / 8, 256>>>(p, shapes, lvl_idx);
    // 5) output projection: [BQ,256] @ [256,256] -> d_out, tf32
    {
        dim3 grid(256 / 64, BQ / 128);
        gemm_tc<0, 0><<<grid, 256>>>(heads, W_out, b_out, out, 256, Cc);
    }
}